// round 7
// baseline (speedup 1.0000x reference)
#include <cuda_runtime.h>
#include <math.h>

#define NPTS 16384
#define NCELL 24
#define NCELL3 13824
#define INV_CELL 0.1875f            // NCELL / 128
#define CELLSZ 5.3333333f           // 128 / NCELL
#define BLK 256
#define NBLK 128                    // 2*NPTS / BLK -> all-resident, 1 wave
#define CCHUNK 54                   // ceil(NCELL3 / 256)
#define ZCHUNK 216                  // 2*NCELL3 / NBLK

__device__ int g_cnt[2][NCELL3];
__device__ int g_start[2][NCELL3 + 1];
__device__ int g_cursor[2][NCELL3];
__device__ float4 g_pts[2][NPTS];   // cell-sorted; w = -0.5*||p||^2
__device__ float g_acc;
__device__ int g_sync[5];           // arrive1, flag1, arrive2, flag2, arrive3

__global__ __launch_bounds__(BLK) void asd_kernel(const float* __restrict__ A,
                                                  const float* __restrict__ B,
                                                  float* __restrict__ out) {
    __shared__ int sh[BLK];
    __shared__ int s_last;
    int tid = threadIdx.x;
    int i = blockIdx.x * BLK + tid;        // 0 .. 2*NPTS-1
    int set = i >> 14;
    int idx = i & (NPTS - 1);
    const float* __restrict__ P = set ? B : A;

    // ---- Phase 1: bin count (point + cell stay in registers) ----
    float x = P[3 * idx], y = P[3 * idx + 1], z = P[3 * idx + 2];
    int cx = min((int)(x * INV_CELL), NCELL - 1);
    int cy = min((int)(y * INV_CELL), NCELL - 1);
    int cz = min((int)(z * INV_CELL), NCELL - 1);
    int c = (cx * NCELL + cy) * NCELL + cz;
    float4 pt = make_float4(x, y, z, -0.5f * (x * x + y * y + z * z));
    atomicAdd(&g_cnt[set][c], 1);

    // ---- Grid sync 1; last-arriving block performs the scan ----
    __threadfence();
    if (tid == 0) s_last = (atomicAdd(&g_sync[0], 1) == NBLK - 1);
    __syncthreads();
    if (s_last) {
        for (int s = 0; s < 2; s++) {
            int base = tid * CCHUNK;
            int sum = 0;
            for (int u = 0; u < CCHUNK; u++) {
                int cc = base + u;
                if (cc < NCELL3) sum += g_cnt[s][cc];
            }
            sh[tid] = sum;
            __syncthreads();
            for (int off = 1; off < BLK; off <<= 1) {
                int v = sh[tid];
                int w = (tid >= off) ? sh[tid - off] : 0;
                __syncthreads();
                sh[tid] = v + w;
                __syncthreads();
            }
            int excl = (tid == 0) ? 0 : sh[tid - 1];
            for (int u = 0; u < CCHUNK; u++) {
                int cc = base + u;
                if (cc < NCELL3) {
                    g_start[s][cc] = excl;
                    g_cursor[s][cc] = excl;
                    excl += g_cnt[s][cc];
                }
            }
            if (tid == BLK - 1) g_start[s][NCELL3] = excl;
            __syncthreads();
        }
        __threadfence();
        if (tid == 0) atomicExch(&g_sync[1], 1);
    } else {
        if (tid == 0) {
            while (atomicAdd(&g_sync[1], 0) == 0) __nanosleep(40);
        }
        __syncthreads();
    }

    // g_cnt no longer needed: re-zero distributed slices for the next replay
    for (int j = tid; j < ZCHUNK; j += BLK)
        ((int*)g_cnt)[blockIdx.x * ZCHUNK + j] = 0;

    // ---- Phase 2: scatter from registers ----
    int pos = atomicAdd(&g_cursor[set][c], 1);
    g_pts[set][pos] = pt;

    // ---- Grid sync 2 ----
    __threadfence();
    __syncthreads();
    if (tid == 0) {
        int t = atomicAdd(&g_sync[2], 1);
        if (t == NBLK - 1) atomicExch(&g_sync[3], 1);
        else { while (atomicAdd(&g_sync[3], 0) == 0) __nanosleep(40); }
    }
    __syncthreads();

    // ---- Phase 3: NN query (thread i = i-th cell-sorted point of its set) ----
    int rs = set ^ 1;
    float4 q = g_pts[set][idx];
    int qx = min((int)(q.x * INV_CELL), NCELL - 1);
    int qy = min((int)(q.y * INV_CELL), NCELL - 1);
    int qz = min((int)(q.z * INV_CELL), NCELL - 1);

    const int* __restrict__ start = g_start[rs];
    const float4* __restrict__ pts = g_pts[rs];

    float best = -1e30f;   // max over refs of e = q.r - 0.5*||r||^2
    for (int r = 1; r <= NCELL; r++) {
        int x0 = max(qx - r, 0), x1 = min(qx + r, NCELL - 1);
        int y0 = max(qy - r, 0), y1 = min(qy + r, NCELL - 1);
        int z0 = max(qz - r, 0), z1 = min(qz + r, NCELL - 1);
        for (int ix = x0; ix <= x1; ix++) {
            for (int iy = y0; iy <= y1; iy++) {
                int base = (ix * NCELL + iy) * NCELL;
                int p0 = start[base + z0];
                int p1 = start[base + z1 + 1];   // contiguous z-span
                for (int p = p0; p < p1; p++) {
                    float4 t = pts[p];
                    float e = fmaf(q.x, t.x, fmaf(q.y, t.y, fmaf(q.z, t.z, t.w)));
                    best = fmaxf(best, e);
                }
            }
        }
        float d2 = -2.0f * (q.w + best);
        float rb = r * CELLSZ;
        if (d2 <= rb * rb) break;   // all unscanned points strictly farther
    }

    float d2 = -2.0f * (q.w + best);
    float v = sqrtf(fmaxf(d2, 0.0f));

    // ---- Block sum, then last-arriving block writes output + resets state ----
    #pragma unroll
    for (int o = 16; o > 0; o >>= 1) v += __shfl_down_sync(0xFFFFFFFFu, v, o);
    float* redf = (float*)sh;
    int lane = tid & 31, wid = tid >> 5;
    __syncthreads();                 // protect sh reuse
    if (lane == 0) redf[wid] = v;
    __syncthreads();
    if (tid == 0) {
        float bs = 0.0f;
        #pragma unroll
        for (int w = 0; w < BLK / 32; w++) bs += redf[w];
        atomicAdd(&g_acc, bs);
        __threadfence();
        int t = atomicAdd(&g_sync[4], 1);
        if (t == NBLK - 1) {
            float total = *((volatile float*)&g_acc);
            out[0] = total * (1.0f / (2.0f * NPTS));
            g_acc = 0.0f;
            g_sync[0] = 0; g_sync[1] = 0; g_sync[2] = 0;
            g_sync[3] = 0; g_sync[4] = 0;
        }
    }
}

extern "C" void kernel_launch(void* const* d_in, const int* in_sizes, int n_in,
                              void* d_out, int out_size) {
    const float* a = (const float*)d_in[0];
    const float* b = (const float*)d_in[1];
    float* out = (float*)d_out;
    asd_kernel<<<NBLK, BLK>>>(a, b, out);
}

// round 8
// speedup vs baseline: 1.1749x; 1.1749x over previous
#include <cuda_runtime.h>
#include <math.h>

#define NPTS 16384
#define NCELL 24
#define NCELL3 13824
#define INV_CELL 0.1875f            // NCELL / 128
#define CELLSZ 5.3333333f           // 128 / NCELL
#define SCAN_T 1024
#define CHUNK 14                    // ceil(13824 / 1024)
#define QBLK 128
#define NQBLK ((2 * NPTS) / QBLK)   // 256 query blocks

__device__ int g_cnt[2][NCELL3];
__device__ int g_start[2][NCELL3 + 1];
__device__ int g_cursor[2][NCELL3];
__device__ float4 g_pts[2][NPTS];   // cell-sorted; w = -0.5*||p||^2
__device__ float g_acc;
__device__ int g_done;

__device__ __forceinline__ int cell_of(float x, float y, float z,
                                       int& cx, int& cy, int& cz) {
    cx = min((int)(x * INV_CELL), NCELL - 1);
    cy = min((int)(y * INV_CELL), NCELL - 1);
    cz = min((int)(z * INV_CELL), NCELL - 1);
    return (cx * NCELL + cy) * NCELL + cz;
}

__global__ void count_kernel(const float* __restrict__ A,
                             const float* __restrict__ B) {
    int i = blockIdx.x * blockDim.x + threadIdx.x;   // 0 .. 2*NPTS-1
    int set = i >> 14;
    int idx = i & (NPTS - 1);
    const float* __restrict__ P = set ? B : A;
    float x = P[3 * idx], y = P[3 * idx + 1], z = P[3 * idx + 2];
    int cx, cy, cz;
    atomicAdd(&g_cnt[set][cell_of(x, y, z, cx, cy, cz)], 1);
}

// 2 blocks (one per set): exclusive scan of 13824 counts; re-zero g_cnt after use.
__global__ void scan_kernel() {
    __shared__ int sh[SCAN_T];
    int set = blockIdx.x;
    int t = threadIdx.x;
    int base = t * CHUNK;

    int loc[CHUNK];
    int sum = 0;
    #pragma unroll
    for (int u = 0; u < CHUNK; u++) {
        int c = base + u;
        loc[u] = (c < NCELL3) ? g_cnt[set][c] : 0;
        sum += loc[u];
    }
    sh[t] = sum;
    __syncthreads();
    for (int off = 1; off < SCAN_T; off <<= 1) {
        int v = sh[t];
        int w = (t >= off) ? sh[t - off] : 0;
        __syncthreads();
        sh[t] = v + w;
        __syncthreads();
    }
    int excl = (t == 0) ? 0 : sh[t - 1];
    #pragma unroll
    for (int u = 0; u < CHUNK; u++) {
        int c = base + u;
        if (c < NCELL3) {
            g_start[set][c] = excl;
            g_cursor[set][c] = excl;
            g_cnt[set][c] = 0;          // ready for next graph replay
            excl += loc[u];
        }
    }
    if (t == SCAN_T - 1) g_start[set][NCELL3] = excl;   // = NPTS
}

__global__ void scatter_kernel(const float* __restrict__ A,
                               const float* __restrict__ B) {
    int i = blockIdx.x * blockDim.x + threadIdx.x;
    int set = i >> 14;
    int idx = i & (NPTS - 1);
    const float* __restrict__ P = set ? B : A;
    float x = P[3 * idx], y = P[3 * idx + 1], z = P[3 * idx + 2];
    int cx, cy, cz;
    int c = cell_of(x, y, z, cx, cy, cz);
    int pos = atomicAdd(&g_cursor[set][c], 1);
    g_pts[set][pos] = make_float4(x, y, z, -0.5f * (x * x + y * y + z * z));
}

// One thread per cell-sorted query; fused final reduction + output.
__global__ __launch_bounds__(QBLK) void query_kernel(float* __restrict__ out) {
    __shared__ float red[QBLK / 32];
    int i = blockIdx.x * QBLK + threadIdx.x;   // 0 .. 2*NPTS-1
    int qs = i >> 14;
    int rs = qs ^ 1;
    int idx = i & (NPTS - 1);

    float4 q = g_pts[qs][idx];
    int qx = min((int)(q.x * INV_CELL), NCELL - 1);
    int qy = min((int)(q.y * INV_CELL), NCELL - 1);
    int qz = min((int)(q.z * INV_CELL), NCELL - 1);

    const int* __restrict__ start = g_start[rs];
    const float4* __restrict__ pts = g_pts[rs];

    float best = -1e30f;   // max over refs of e = q.r - 0.5*||r||^2

    // ---- radius-1 fast path: prefetch all span bounds (high MLP) ----
    {
        int x0 = max(qx - 1, 0), x1 = min(qx + 1, NCELL - 1);
        int y0 = max(qy - 1, 0), y1 = min(qy + 1, NCELL - 1);
        int z0 = max(qz - 1, 0), z1 = min(qz + 1, NCELL - 1);
        int sp0[9], sp1[9];
        int np = 0;
        for (int ix = x0; ix <= x1; ix++)
            for (int iy = y0; iy <= y1; iy++) {
                int base = (ix * NCELL + iy) * NCELL;
                sp0[np] = __ldg(&start[base + z0]);
                sp1[np] = __ldg(&start[base + z1 + 1]);
                np++;
            }
        for (int s = 0; s < np; s++)
            for (int p = sp0[s]; p < sp1[s]; p++) {
                float4 t = pts[p];
                float e = fmaf(q.x, t.x, fmaf(q.y, t.y, fmaf(q.z, t.z, t.w)));
                best = fmaxf(best, e);
            }
    }

    // ---- rare expansion (~0.7%): general loop, rescans interior (correct) ----
    float d2 = -2.0f * (q.w + best);
    if (d2 > CELLSZ * CELLSZ) {
        for (int r = 2; r <= NCELL; r++) {
            int x0 = max(qx - r, 0), x1 = min(qx + r, NCELL - 1);
            int y0 = max(qy - r, 0), y1 = min(qy + r, NCELL - 1);
            int z0 = max(qz - r, 0), z1 = min(qz + r, NCELL - 1);
            for (int ix = x0; ix <= x1; ix++)
                for (int iy = y0; iy <= y1; iy++) {
                    int base = (ix * NCELL + iy) * NCELL;
                    int p0 = start[base + z0];
                    int p1 = start[base + z1 + 1];
                    for (int p = p0; p < p1; p++) {
                        float4 t = pts[p];
                        float e = fmaf(q.x, t.x, fmaf(q.y, t.y, fmaf(q.z, t.z, t.w)));
                        best = fmaxf(best, e);
                    }
                }
            d2 = -2.0f * (q.w + best);
            float rb = r * CELLSZ;
            if (d2 <= rb * rb) break;
        }
    }

    float v = sqrtf(fmaxf(d2, 0.0f));

    // ---- block sum -> global atomic; last block writes out + resets state ----
    #pragma unroll
    for (int o = 16; o > 0; o >>= 1) v += __shfl_down_sync(0xFFFFFFFFu, v, o);
    int lane = threadIdx.x & 31, wid = threadIdx.x >> 5;
    if (lane == 0) red[wid] = v;
    __syncthreads();
    if (threadIdx.x == 0) {
        float bs = 0.0f;
        #pragma unroll
        for (int w = 0; w < QBLK / 32; w++) bs += red[w];
        atomicAdd(&g_acc, bs);
        __threadfence();
        int t = atomicAdd(&g_done, 1);
        if (t == NQBLK - 1) {
            float total = *((volatile float*)&g_acc);
            out[0] = total * (1.0f / (2.0f * NPTS));
            g_acc = 0.0f;                 // reset for next graph replay
            g_done = 0;
        }
    }
}

extern "C" void kernel_launch(void* const* d_in, const int* in_sizes, int n_in,
                              void* d_out, int out_size) {
    const float* a = (const float*)d_in[0];
    const float* b = (const float*)d_in[1];
    float* out = (float*)d_out;

    count_kernel<<<(2 * NPTS) / 256, 256>>>(a, b);
    scan_kernel<<<2, SCAN_T>>>();
    scatter_kernel<<<(2 * NPTS) / 256, 256>>>(a, b);
    query_kernel<<<NQBLK, QBLK>>>(out);
}